// round 11
// baseline (speedup 1.0000x reference)
#include <cuda_runtime.h>

#define TT 512
#define BB 32
#define HH 512
#define NREC 128
#define XW_COLS 16384            // T*B
#define XW_ROWS 4096             // 2 dirs * 4 gates * H

// h double buffer, TRANSPOSED layout: float index = (j>>2)*128 + b*4 + (j&3)
__device__ float g_h[2][2][BB * HH];
__device__ unsigned int g_flags[NREC];      // monotonic barrier flags
__device__ unsigned int g_dead;             // timeout poison
__device__ float g_xw[(size_t)XW_ROWS * XW_COLS];   // 256MB scratch: XW[r][n]

typedef unsigned long long ull;

static __device__ __forceinline__ ull pk(float x, float y) {
    ull r; asm("mov.b64 %0,{%1,%2};" : "=l"(r) : "f"(x), "f"(y)); return r;
}
static __device__ __forceinline__ void up(ull v, float& x, float& y) {
    asm("mov.b64 {%0,%1},%2;" : "=f"(x), "=f"(y) : "l"(v));
}
static __device__ __forceinline__ ull fma2(ull a, ull b, ull c) {
    ull d; asm("fma.rn.f32x2 %0,%1,%2,%3;" : "=l"(d) : "l"(a), "l"(b), "l"(c)); return d;
}
static __device__ __forceinline__ ull add2(ull a, ull b) {
    ull d; asm("add.rn.f32x2 %0,%1,%2;" : "=l"(d) : "l"(a), "l"(b)); return d;
}
static __device__ __forceinline__ float sigm(float x) {
    return __fdividef(1.f, 1.f + __expf(-x));
}
static __device__ __forceinline__ float tanh_(float x) {
    float a = fabsf(x), e = __expf(-2.f * a);
    return copysignf(__fdividef(1.f - e, 1.f + e), x);
}

// ---------------- embedding gather: out_emb[T][B][H] = emb[seq] ----------------
__global__ void embed_kernel(const int* __restrict__ seq,
                             const float* __restrict__ emb,
                             float* __restrict__ out_emb)
{
    int gw = blockIdx.x * 8 + (threadIdx.x >> 5);
    int lane = threadIdx.x & 31;
    const float4* ev = (const float4*)emb;
    float4* dv = (float4*)out_emb;
    for (int n = gw; n < TT * BB; n += gridDim.x * 8) {
        int tok = __ldg(seq + n);
        const float4* s = ev + (size_t)tok * (HH / 4);
        float4* d = dv + (size_t)n * (HH / 4);
#pragma unroll
        for (int i = 0; i < 4; i++) d[lane + i * 32] = __ldg(s + lane + i * 32);
    }
}

// ---------------- XW GEMM: g_xw[r][n] = sum_k W[r][k] * X[n][k] ----------------
__global__ void __launch_bounds__(256, 1) xw_gemm_kernel(
    const float* __restrict__ Wih_f, const float* __restrict__ Wih_b,
    const float* __restrict__ X)
{
    __shared__ float As[16][132];
    __shared__ float Bs[16][68];
    const int tid = threadIdx.x;
    const int mt = blockIdx.x & 31, nt = blockIdx.x >> 5;
    const int m0 = mt * 128, n0 = nt * 64;
    const float* A = (m0 < 2048) ? (Wih_f + (size_t)m0 * HH)
                                 : (Wih_b + (size_t)(m0 - 2048) * HH);
    const int ar = tid >> 1, af = (tid & 1) * 2;
    const int br = tid >> 2, bf = tid & 3;
    const int tm = tid >> 4, tn = tid & 15;

    float4 ra0, ra1, rb;
    {
        const float4* Ap = (const float4*)(A + (size_t)ar * HH);
        ra0 = Ap[af]; ra1 = Ap[af + 1];
        rb = ((const float4*)(X + (size_t)(n0 + br) * HH))[bf];
    }
    ull acc[4][4];
#pragma unroll
    for (int i = 0; i < 4; i++)
#pragma unroll
        for (int n = 0; n < 4; n++) acc[i][n] = 0;

    for (int c = 0; c < 32; c++) {
        {
            const int kb = af * 4;
            As[kb + 0][ar] = ra0.x; As[kb + 1][ar] = ra0.y;
            As[kb + 2][ar] = ra0.z; As[kb + 3][ar] = ra0.w;
            As[kb + 4][ar] = ra1.x; As[kb + 5][ar] = ra1.y;
            As[kb + 6][ar] = ra1.z; As[kb + 7][ar] = ra1.w;
            const int kc = bf * 4;
            Bs[kc + 0][br] = rb.x; Bs[kc + 1][br] = rb.y;
            Bs[kc + 2][br] = rb.z; Bs[kc + 3][br] = rb.w;
        }
        __syncthreads();
        if (c < 31) {
            const int k0 = (c + 1) * 16;
            const float4* Ap = (const float4*)(A + (size_t)ar * HH + k0);
            ra0 = Ap[af]; ra1 = Ap[af + 1];
            rb = ((const float4*)(X + (size_t)(n0 + br) * HH + k0))[bf];
        }
#pragma unroll
        for (int k = 0; k < 16; k++) {
            float4 va = *(const float4*)&As[k][tm * 8];
            float4 vb = *(const float4*)&As[k][tm * 8 + 4];
            float4 vn = *(const float4*)&Bs[k][tn * 4];
            ull ap0 = pk(va.x, va.y), ap1 = pk(va.z, va.w);
            ull ap2 = pk(vb.x, vb.y), ap3 = pk(vb.z, vb.w);
            ull b0 = pk(vn.x, vn.x), b1 = pk(vn.y, vn.y);
            ull b2 = pk(vn.z, vn.z), b3 = pk(vn.w, vn.w);
            acc[0][0] = fma2(ap0, b0, acc[0][0]); acc[0][1] = fma2(ap0, b1, acc[0][1]);
            acc[0][2] = fma2(ap0, b2, acc[0][2]); acc[0][3] = fma2(ap0, b3, acc[0][3]);
            acc[1][0] = fma2(ap1, b0, acc[1][0]); acc[1][1] = fma2(ap1, b1, acc[1][1]);
            acc[1][2] = fma2(ap1, b2, acc[1][2]); acc[1][3] = fma2(ap1, b3, acc[1][3]);
            acc[2][0] = fma2(ap2, b0, acc[2][0]); acc[2][1] = fma2(ap2, b1, acc[2][1]);
            acc[2][2] = fma2(ap2, b2, acc[2][2]); acc[2][3] = fma2(ap2, b3, acc[2][3]);
            acc[3][0] = fma2(ap3, b0, acc[3][0]); acc[3][1] = fma2(ap3, b1, acc[3][1]);
            acc[3][2] = fma2(ap3, b2, acc[3][2]); acc[3][3] = fma2(ap3, b3, acc[3][3]);
        }
        __syncthreads();
    }
#pragma unroll
    for (int i = 0; i < 4; i++) {
        const int m = m0 + tm * 8 + i * 2;
#pragma unroll
        for (int n = 0; n < 4; n++) {
            float lo, hi; up(acc[i][n], lo, hi);
            size_t base = (size_t)m * XW_COLS + n0 + tn * 4 + n;
            g_xw[base] = lo;
            g_xw[base + XW_COLS] = hi;
        }
    }
}

// fused barrier among 64 blocks of a direction; monotonic, wrap-safe, timeout-poisoned
static __device__ __forceinline__ void gbar(int dir, int bid, unsigned int tgt) {
    __threadfence();
    __syncthreads();
    if (threadIdx.x < 32) {
        if (threadIdx.x == 0) atomicExch(&g_flags[bid], tgt);
        volatile unsigned int* f = g_flags + dir * 64;
        volatile unsigned int* dead = &g_dead;
        unsigned int it = 0;
        bool ok;
        do {
            unsigned int a = f[threadIdx.x], b = f[threadIdx.x + 32];
            ok = ((int)(a - tgt) >= 0) && ((int)(b - tgt) >= 0);
            if (++it > (1u << 18)) {
                if (threadIdx.x == 0) atomicExch(&g_dead, 1u);
                break;
            }
        } while (!__all_sync(0xffffffffu, ok) && *dead == 0u);
        __threadfence();
    }
    __syncthreads();
}

// dynamic SMEM: packed Whh pairs only (64KB) — h is read straight from L2
extern __shared__ float dyn_sm[];

// ---------------- serial recurrence: h-part only; lane = batch ----------------
__global__ void __launch_bounds__(256, 1) bilstm_loop_kernel(
    const int* __restrict__ lens,
    const float* __restrict__ Whh_f, const float* __restrict__ bih_f, const float* __restrict__ bhh_f,
    const float* __restrict__ Whh_b, const float* __restrict__ bih_b, const float* __restrict__ bhh_b,
    float* __restrict__ out)
{
    const int bid = blockIdx.x, tid = threadIdx.x;
    const int w = tid >> 5, lane = tid & 31;      // lane = batch index
    const int dir = bid >> 6;
    const int j0 = (bid & 63) * 8;
    const int j = j0 + w;                         // this warp's hidden unit

    ull* w01_sm = (ull*)dyn_sm;                   // [8][512] packed (i,f)
    ull* w23_sm = w01_sm + 8 * 512;               // [8][512] packed (g,o)

    float* out_outputs = out;                             // [T][B][2][H]
    float* out_hidden  = out + (size_t)TT * BB * 2 * HH;  // [2][T][B][H]

    const float* Whh = dir ? Whh_b : Whh_f;
    const float* bih = dir ? bih_b : bih_f;
    const float* bhh = dir ? bhh_b : bhh_f;

    const float bi = bih[j] + bhh[j];
    const float bf = bih[HH + j] + bhh[HH + j];
    const float bg = bih[2 * HH + j] + bhh[2 * HH + j];
    const float bo = bih[3 * HH + j] + bhh[3 * HH + j];

    // preload Whh slice of unit j into SMEM as packed (i,f)/(g,o) pairs (once)
    for (int k0 = lane * 4; k0 < HH; k0 += 128) {
        float4 vi = *(const float4*)(Whh + (size_t)j * HH + k0);
        float4 vf = *(const float4*)(Whh + (size_t)(HH + j) * HH + k0);
        float4 vg = *(const float4*)(Whh + (size_t)(2 * HH + j) * HH + k0);
        float4 vo = *(const float4*)(Whh + (size_t)(3 * HH + j) * HH + k0);
        ull* W01 = w01_sm + w * 512 + k0;
        ull* W23 = w23_sm + w * 512 + k0;
        W01[0] = pk(vi.x, vf.x); W23[0] = pk(vg.x, vo.x);
        W01[1] = pk(vi.y, vf.y); W23[1] = pk(vg.y, vo.y);
        W01[2] = pk(vi.z, vf.z); W23[2] = pk(vg.z, vo.z);
        W01[3] = pk(vi.w, vf.w); W23[3] = pk(vg.w, vo.w);
    }

    __shared__ float hb_h[8][33], hb_o[8][33];

    {   // zero initial h (parity 0) in transposed layout, via epilogue mapping
        int b = tid >> 3, jl = tid & 7, jj = j0 + jl;
        __stcg(&g_h[dir][0][(jj >> 2) * 128 + b * 4 + (jj & 3)], 0.f);
    }
    __syncthreads();    // weights staged

    float c_state = 0.f, h_state = 0.f;                   // lane = batch
    const int mylen = __ldg(lens + lane);
    unsigned int tgt = g_flags[bid];
    gbar(dir, bid, ++tgt);

    const float* xwj = g_xw + (size_t)(dir * 2048 + j) * XW_COLS + lane;
    const ull* W01 = w01_sm + w * 512;
    const ull* W23 = w23_sm + w * 512;

    for (int t = 0; t < TT; t++) {
        const int tt = dir ? (TT - 1 - t) : t;
        const float* hcur = g_h[dir][t & 1];
        float* hnxt = g_h[dir][(t & 1) ^ 1];

        // precomputed x-gates (coalesced; latency hidden under the dot product)
        const float* xp = xwj + tt * 32;
        float xg0 = __ldg(xp);
        float xg1 = __ldg(xp + (size_t)512 * XW_COLS);
        float xg2 = __ldg(xp + (size_t)1024 * XW_COLS);
        float xg3 = __ldg(xp + (size_t)1536 * XW_COLS);

        // full-K dot product per lane (= batch).
        // h read directly from L2 (__ldcg: other SMs wrote it; transposed layout
        // makes the warp's float4 loads 512B-contiguous = fully coalesced).
        ull aif0 = 0, aif1 = 0, ago0 = 0, ago1 = 0;
        const float4* hp4 = (const float4*)hcur + lane;   // [kc][b] float4
#pragma unroll 8
        for (int kc = 0; kc < 128; kc++) {
            float4 h4 = __ldcg(hp4 + kc * 32);
            ull d0 = pk(h4.x, h4.x), d1 = pk(h4.y, h4.y);
            ull d2 = pk(h4.z, h4.z), d3 = pk(h4.w, h4.w);
            aif0 = fma2(W01[4 * kc + 0], d0, aif0); ago0 = fma2(W23[4 * kc + 0], d0, ago0);
            aif1 = fma2(W01[4 * kc + 1], d1, aif1); ago1 = fma2(W23[4 * kc + 1], d1, ago1);
            aif0 = fma2(W01[4 * kc + 2], d2, aif0); ago0 = fma2(W23[4 * kc + 2], d2, ago0);
            aif1 = fma2(W01[4 * kc + 3], d3, aif1); ago1 = fma2(W23[4 * kc + 3], d3, ago1);
        }
        float gi, gf, gg, go;
        up(add2(aif0, aif1), gi, gf);
        up(add2(ago0, ago1), gg, go);

        // gates (lane = batch)
        float iv = sigm(gi + xg0 + bi), fv = sigm(gf + xg1 + bf);
        float gv = tanh_(gg + xg2 + bg), ov = sigm(go + xg3 + bo);
        float cn = fv * c_state + iv * gv;
        float hn = ov * tanh_(cn);
        const bool m = (tt < mylen);
        h_state = m ? hn : h_state;
        c_state = m ? cn : c_state;
        float oz = m ? hn : 0.f;

        hb_h[w][lane] = h_state;
        hb_o[w][lane] = oz;
        __syncthreads();

        {   // epilogue: thread -> (b = tid>>3, jl = tid&7)
            int b = tid >> 3, jl = tid & 7, jj = j0 + jl;
            float hs_ = hb_h[jl][b], os_ = hb_o[jl][b];
            __stcg(&hnxt[(jj >> 2) * 128 + b * 4 + (jj & 3)], hs_);   // transposed h
            out_outputs[((size_t)(tt * BB + b) * 2 + dir) * HH + jj] = os_;
            out_hidden[((size_t)(dir * TT + tt) * BB + b) * HH + jj] = os_;
        }

        gbar(dir, bid, ++tgt);
    }
}

extern "C" void kernel_launch(void* const* d_in, const int* in_sizes, int n_in,
                              void* d_out, int out_size) {
    (void)in_sizes; (void)n_in; (void)out_size;
    const int*   seq   = (const int*)d_in[0];
    const int*   lens  = (const int*)d_in[1];
    const float* emb   = (const float*)d_in[2];
    const float* Wih_f = (const float*)d_in[3];
    const float* Whh_f = (const float*)d_in[4];
    const float* bih_f = (const float*)d_in[5];
    const float* bhh_f = (const float*)d_in[6];
    const float* Wih_b = (const float*)d_in[7];
    const float* Whh_b = (const float*)d_in[8];
    const float* bih_b = (const float*)d_in[9];
    const float* bhh_b = (const float*)d_in[10];
    float* out = (float*)d_out;
    float* out_emb = out + (size_t)4 * TT * BB * HH;

    const int loop_smem = 8 * 512 * 2 * (int)sizeof(ull);   // 64KB (same as passing R8)
    cudaFuncSetAttribute(bilstm_loop_kernel, cudaFuncAttributeMaxDynamicSharedMemorySize,
                         loop_smem);

    embed_kernel<<<148, 256>>>(seq, emb, out_emb);
    xw_gemm_kernel<<<(XW_ROWS / 128) * (XW_COLS / 64), 256>>>(Wih_f, Wih_b, out_emb);
    bilstm_loop_kernel<<<NREC, 256, loop_smem>>>(
        lens, Whh_f, bih_f, bhh_f, Whh_b, bih_b, bhh_b, out);
}

// round 14
// speedup vs baseline: 1.0225x; 1.0225x over previous
#include <cuda_runtime.h>

#define TT 512
#define BB 32
#define HH 512
#define NREC 128
#define XW_COLS 16384            // T*B
#define XW_ROWS 4096             // 2 dirs * 4 gates * H

// h double buffer, TRANSPOSED layout: float index = (j>>2)*128 + b*4 + (j&3)
__device__ float g_h[2][2][BB * HH];
__device__ unsigned int g_flags[NREC];      // monotonic barrier flags
__device__ unsigned int g_dead;             // timeout poison
__device__ float g_xw[(size_t)XW_ROWS * XW_COLS];   // 256MB scratch: XW[r][n]

typedef unsigned long long ull;

static __device__ __forceinline__ ull pk(float x, float y) {
    ull r; asm("mov.b64 %0,{%1,%2};" : "=l"(r) : "f"(x), "f"(y)); return r;
}
static __device__ __forceinline__ void up(ull v, float& x, float& y) {
    asm("mov.b64 {%0,%1},%2;" : "=f"(x), "=f"(y) : "l"(v));
}
static __device__ __forceinline__ ull fma2(ull a, ull b, ull c) {
    ull d; asm("fma.rn.f32x2 %0,%1,%2,%3;" : "=l"(d) : "l"(a), "l"(b), "l"(c)); return d;
}
static __device__ __forceinline__ ull add2(ull a, ull b) {
    ull d; asm("add.rn.f32x2 %0,%1,%2;" : "=l"(d) : "l"(a), "l"(b)); return d;
}
static __device__ __forceinline__ float sigm(float x) {
    return __fdividef(1.f, 1.f + __expf(-x));
}
static __device__ __forceinline__ float tanh_(float x) {
    float a = fabsf(x), e = __expf(-2.f * a);
    return copysignf(__fdividef(1.f - e, 1.f + e), x);
}

// ---------------- embedding gather: out_emb[T][B][H] = emb[seq] ----------------
__global__ void embed_kernel(const int* __restrict__ seq,
                             const float* __restrict__ emb,
                             float* __restrict__ out_emb)
{
    const int gw = blockIdx.x * 8 + (threadIdx.x >> 5);
    const int lane = threadIdx.x & 31;
    const float4* ev = (const float4*)emb;
    float4* dv = (float4*)out_emb;
    for (int n = gw; n < TT * BB; n += gridDim.x * 8) {
        const int tok = __ldg(seq + n);
        const float4* s = ev + (size_t)tok * (HH / 4);
        float4* d = dv + (size_t)n * (HH / 4);
#pragma unroll
        for (int i = 0; i < 4; i++) d[lane + i * 32] = __ldg(s + lane + i * 32);
    }
}

// ---------------- XW GEMM: g_xw[r][n] = sum_k W[r][k] * X[n][k] ----------------
__global__ void __launch_bounds__(256, 1) xw_gemm_kernel(
    const float* __restrict__ Wih_f, const float* __restrict__ Wih_b,
    const float* __restrict__ X)
{
    __shared__ float As[16][132];
    __shared__ float Bs[16][68];
    const int tid = threadIdx.x;
    const int mt = blockIdx.x & 31, nt = blockIdx.x >> 5;
    const int m0 = mt * 128, n0 = nt * 64;
    const float* A = (m0 < 2048) ? (Wih_f + (size_t)m0 * HH)
                                 : (Wih_b + (size_t)(m0 - 2048) * HH);
    const int ar = tid >> 1, af = (tid & 1) * 2;
    const int br = tid >> 2, bf = tid & 3;
    const int tm = tid >> 4, tn = tid & 15;

    float4 ra0, ra1, rb;
    {
        const float4* Ap = (const float4*)(A + (size_t)ar * HH);
        ra0 = Ap[af]; ra1 = Ap[af + 1];
        rb = ((const float4*)(X + (size_t)(n0 + br) * HH))[bf];
    }
    ull acc[4][4];
#pragma unroll
    for (int i = 0; i < 4; i++)
#pragma unroll
        for (int n = 0; n < 4; n++) acc[i][n] = 0;

    for (int c = 0; c < 32; c++) {
        {
            const int kb = af * 4;
            As[kb + 0][ar] = ra0.x; As[kb + 1][ar] = ra0.y;
            As[kb + 2][ar] = ra0.z; As[kb + 3][ar] = ra0.w;
            As[kb + 4][ar] = ra1.x; As[kb + 5][ar] = ra1.y;
            As[kb + 6][ar] = ra1.z; As[kb + 7][ar] = ra1.w;
            const int kc = bf * 4;
            Bs[kc + 0][br] = rb.x; Bs[kc + 1][br] = rb.y;
            Bs[kc + 2][br] = rb.z; Bs[kc + 3][br] = rb.w;
        }
        __syncthreads();
        if (c < 31) {
            const int k0 = (c + 1) * 16;
            const float4* Ap = (const float4*)(A + (size_t)ar * HH + k0);
            ra0 = Ap[af]; ra1 = Ap[af + 1];
            rb = ((const float4*)(X + (size_t)(n0 + br) * HH + k0))[bf];
        }
#pragma unroll
        for (int k = 0; k < 16; k++) {
            float4 va = *(const float4*)&As[k][tm * 8];
            float4 vb = *(const float4*)&As[k][tm * 8 + 4];
            float4 vn = *(const float4*)&Bs[k][tn * 4];
            ull ap0 = pk(va.x, va.y), ap1 = pk(va.z, va.w);
            ull ap2 = pk(vb.x, vb.y), ap3 = pk(vb.z, vb.w);
            ull b0 = pk(vn.x, vn.x), b1 = pk(vn.y, vn.y);
            ull b2 = pk(vn.z, vn.z), b3 = pk(vn.w, vn.w);
            acc[0][0] = fma2(ap0, b0, acc[0][0]); acc[0][1] = fma2(ap0, b1, acc[0][1]);
            acc[0][2] = fma2(ap0, b2, acc[0][2]); acc[0][3] = fma2(ap0, b3, acc[0][3]);
            acc[1][0] = fma2(ap1, b0, acc[1][0]); acc[1][1] = fma2(ap1, b1, acc[1][1]);
            acc[1][2] = fma2(ap1, b2, acc[1][2]); acc[1][3] = fma2(ap1, b3, acc[1][3]);
            acc[2][0] = fma2(ap2, b0, acc[2][0]); acc[2][1] = fma2(ap2, b1, acc[2][1]);
            acc[2][2] = fma2(ap2, b2, acc[2][2]); acc[2][3] = fma2(ap2, b3, acc[2][3]);
            acc[3][0] = fma2(ap3, b0, acc[3][0]); acc[3][1] = fma2(ap3, b1, acc[3][1]);
            acc[3][2] = fma2(ap3, b2, acc[3][2]); acc[3][3] = fma2(ap3, b3, acc[3][3]);
        }
        __syncthreads();
    }
#pragma unroll
    for (int i = 0; i < 4; i++) {
        const int m = m0 + tm * 8 + i * 2;
#pragma unroll
        for (int n = 0; n < 4; n++) {
            float lo, hi; up(acc[i][n], lo, hi);
            size_t base = (size_t)m * XW_COLS + n0 + tn * 4 + n;
            g_xw[base] = lo;
            g_xw[base + XW_COLS] = hi;
        }
    }
}

// fused barrier among 64 blocks of a direction; monotonic, wrap-safe, timeout-poisoned
static __device__ __forceinline__ void gbar(int dir, int bid, unsigned int tgt) {
    __threadfence();
    __syncthreads();
    if (threadIdx.x < 32) {
        if (threadIdx.x == 0) atomicExch(&g_flags[bid], tgt);
        volatile unsigned int* f = g_flags + dir * 64;
        volatile unsigned int* dead = &g_dead;
        unsigned int spin = 0;
        bool ok;
        do {
            unsigned int a = f[threadIdx.x], b = f[threadIdx.x + 32];
            ok = ((int)(a - tgt) >= 0) && ((int)(b - tgt) >= 0);
            if (++spin > (1u << 18)) {
                if (threadIdx.x == 0) atomicExch(&g_dead, 1u);
                break;
            }
        } while (!__all_sync(0xffffffffu, ok) && *dead == 0u);
        __threadfence();
    }
    __syncthreads();
}

// dynamic SMEM: packed Whh pairs only (64KB) — h is read straight from L2
extern __shared__ float dyn_sm[];

// ---- serial recurrence, 512 threads: lane = batch, K split across warp-halves.
// Output stores are deferred until after the barrier arrive so the fence only
// drains the recurrence-critical hnxt store.
__global__ void __launch_bounds__(512, 1) bilstm_loop_kernel(
    const int* __restrict__ lens,
    const float* __restrict__ Whh_f, const float* __restrict__ bih_f, const float* __restrict__ bhh_f,
    const float* __restrict__ Whh_b, const float* __restrict__ bih_b, const float* __restrict__ bhh_b,
    float* __restrict__ out)
{
    const int bid = blockIdx.x, tid = threadIdx.x;
    const int w = tid >> 5, lane = tid & 31;      // lane = batch index
    const int u = w & 7;                          // unit-local index 0..7
    const int kh = w >> 3;                        // K-half: 0 -> [0,256), 1 -> [256,512)
    const int dir = bid >> 6;
    const int j0 = (bid & 63) * 8;
    const int j = j0 + u;                         // this warp's hidden unit

    ull* w01_sm = (ull*)dyn_sm;                   // [8][512] packed (i,f)
    ull* w23_sm = w01_sm + 8 * 512;               // [8][512] packed (g,o)

    __shared__ ull psum_if[8][33], psum_go[8][33];    // upper-half partial sums
    __shared__ float hb_h[8][33], hb_o[8][33];

    float* out_outputs = out;                             // [T][B][2][H]
    float* out_hidden  = out + (size_t)TT * BB * 2 * HH;  // [2][T][B][H]

    const float* Whh = dir ? Whh_b : Whh_f;
    const float* bih = dir ? bih_b : bih_f;
    const float* bhh = dir ? bhh_b : bhh_f;

    const float bi = bih[j] + bhh[j];
    const float bf = bih[HH + j] + bhh[HH + j];
    const float bg = bih[2 * HH + j] + bhh[2 * HH + j];
    const float bo = bih[3 * HH + j] + bhh[3 * HH + j];

    // preload Whh slice of unit j into SMEM as packed (i,f)/(g,o) pairs (warps 0-7, once)
    if (w < 8) {
        for (int k0 = lane * 4; k0 < HH; k0 += 128) {
            float4 vi = *(const float4*)(Whh + (size_t)j * HH + k0);
            float4 vf = *(const float4*)(Whh + (size_t)(HH + j) * HH + k0);
            float4 vg = *(const float4*)(Whh + (size_t)(2 * HH + j) * HH + k0);
            float4 vo = *(const float4*)(Whh + (size_t)(3 * HH + j) * HH + k0);
            ull* W01 = w01_sm + w * 512 + k0;
            ull* W23 = w23_sm + w * 512 + k0;
            W01[0] = pk(vi.x, vf.x); W23[0] = pk(vg.x, vo.x);
            W01[1] = pk(vi.y, vf.y); W23[1] = pk(vg.y, vo.y);
            W01[2] = pk(vi.z, vf.z); W23[2] = pk(vg.z, vo.z);
            W01[3] = pk(vi.w, vf.w); W23[3] = pk(vg.w, vo.w);
        }
    }

    if (tid < 256) {   // zero initial h (parity 0) in transposed layout
        const int b = tid >> 3, jl = tid & 7, jj = j0 + jl;
        __stcg(&g_h[dir][0][(jj >> 2) * 128 + b * 4 + (jj & 3)], 0.f);
    }
    __syncthreads();    // weights staged

    float c_state = 0.f, h_state = 0.f;                   // meaningful in lower warps
    const int mylen = __ldg(lens + lane);
    unsigned int tgt = g_flags[bid];
    gbar(dir, bid, ++tgt);

    const float* xwj = g_xw + (size_t)(dir * 2048 + j) * XW_COLS + lane;
    // 16B-aligned views of this warp's K-half of the packed weights
    const ulonglong2* W01v = (const ulonglong2*)(w01_sm + u * 512 + kh * 256);
    const ulonglong2* W23v = (const ulonglong2*)(w23_sm + u * 512 + kh * 256);

    for (int t = 0; t < TT; t++) {
        const int tt = dir ? (TT - 1 - t) : t;
        const float* hcur = g_h[dir][t & 1];
        float* hnxt = g_h[dir][(t & 1) ^ 1];

        // precomputed x-gates (lower warps only; coalesced)
        float xg0 = 0.f, xg1 = 0.f, xg2 = 0.f, xg3 = 0.f;
        if (kh == 0) {
            const float* xp = xwj + tt * 32;
            xg0 = __ldg(xp);
            xg1 = __ldg(xp + (size_t)512 * XW_COLS);
            xg2 = __ldg(xp + (size_t)1024 * XW_COLS);
            xg3 = __ldg(xp + (size_t)1536 * XW_COLS);
        }

        // half-K dot product per lane (= batch); h from L2 (coalesced, __ldcg),
        // weights broadcast from SMEM as 16B loads.
        ull aif0 = 0, aif1 = 0, ago0 = 0, ago1 = 0;
        const float4* hp4 = (const float4*)hcur + kh * (64 * 32) + lane;
#pragma unroll 8
        for (int kc = 0; kc < 64; kc++) {
            float4 h4 = __ldcg(hp4 + kc * 32);
            ulonglong2 wa = W01v[2 * kc], wb = W01v[2 * kc + 1];
            ulonglong2 wc = W23v[2 * kc], wd = W23v[2 * kc + 1];
            ull d0 = pk(h4.x, h4.x), d1 = pk(h4.y, h4.y);
            ull d2 = pk(h4.z, h4.z), d3 = pk(h4.w, h4.w);
            aif0 = fma2(wa.x, d0, aif0); ago0 = fma2(wc.x, d0, ago0);
            aif1 = fma2(wa.y, d1, aif1); ago1 = fma2(wc.y, d1, ago1);
            aif0 = fma2(wb.x, d2, aif0); ago0 = fma2(wd.x, d2, ago0);
            aif1 = fma2(wb.y, d3, aif1); ago1 = fma2(wd.y, d3, ago1);
        }

        if (kh == 1) {   // upper half publishes partial sums
            psum_if[u][lane] = add2(aif0, aif1);
            psum_go[u][lane] = add2(ago0, ago1);
        }
        __syncthreads();

        if (kh == 0) {   // lower half combines, computes gates + state
            ull s_if = add2(add2(aif0, aif1), psum_if[u][lane]);
            ull s_go = add2(add2(ago0, ago1), psum_go[u][lane]);
            float gi, gf, gg, go;
            up(s_if, gi, gf);
            up(s_go, gg, go);

            float iv = sigm(gi + xg0 + bi), fv = sigm(gf + xg1 + bf);
            float gv = tanh_(gg + xg2 + bg), ov = sigm(go + xg3 + bo);
            float cn = fv * c_state + iv * gv;
            float hn = ov * tanh_(cn);
            const bool msk = (tt < mylen);
            h_state = msk ? hn : h_state;
            c_state = msk ? cn : c_state;
            hb_h[u][lane] = h_state;
            hb_o[u][lane] = msk ? hn : 0.f;
        }
        __syncthreads();

        // epilogue split: hnxt (recurrence-critical) before the barrier, output
        // stores (read by nobody) after the arrive, overlapping the next step.
        float os_keep = 0.f;
        int b_e = 0, jj_e = 0;
        if (tid < 256) {
            b_e = tid >> 3;
            const int jl = tid & 7;
            jj_e = j0 + jl;
            const float hs_ = hb_h[jl][b_e];
            os_keep = hb_o[jl][b_e];
            __stcg(&hnxt[(jj_e >> 2) * 128 + b_e * 4 + (jj_e & 3)], hs_);
        }

        gbar(dir, bid, ++tgt);

        if (tid < 256) {
            out_outputs[((size_t)(tt * BB + b_e) * 2 + dir) * HH + jj_e] = os_keep;
            out_hidden[((size_t)(dir * TT + tt) * BB + b_e) * HH + jj_e] = os_keep;
        }
    }
}

extern "C" void kernel_launch(void* const* d_in, const int* in_sizes, int n_in,
                              void* d_out, int out_size) {
    (void)in_sizes; (void)n_in; (void)out_size;
    const int*   seq   = (const int*)d_in[0];
    const int*   lens  = (const int*)d_in[1];
    const float* emb   = (const float*)d_in[2];
    const float* Wih_f = (const float*)d_in[3];
    const float* Whh_f = (const float*)d_in[4];
    const float* bih_f = (const float*)d_in[5];
    const float* bhh_f = (const float*)d_in[6];
    const float* Wih_b = (const float*)d_in[7];
    const float* Whh_b = (const float*)d_in[8];
    const float* bih_b = (const float*)d_in[9];
    const float* bhh_b = (const float*)d_in[10];
    float* out = (float*)d_out;
    float* out_emb = out + (size_t)4 * TT * BB * HH;

    const int loop_smem = 8 * 512 * 2 * (int)sizeof(ull);   // 64KB dynamic
    cudaFuncSetAttribute(bilstm_loop_kernel, cudaFuncAttributeMaxDynamicSharedMemorySize,
                         loop_smem);

    embed_kernel<<<148, 256>>>(seq, emb, out_emb);
    xw_gemm_kernel<<<(XW_ROWS / 128) * (XW_COLS / 64), 256>>>(Wih_f, Wih_b, out_emb);
    bilstm_loop_kernel<<<NREC, 512, loop_smem>>>(
        lens, Whh_f, bih_f, bhh_f, Whh_b, bih_b, bhh_b, out);
}